// round 1
// baseline (speedup 1.0000x reference)
#include <cuda_runtime.h>

#define NTOK 16384
#define NEXP 64
#define DIM  2048
#define KC   64
#define TOK_PER_BLK 64
#define THREADS 256
#define XPAD 4   // Xsm row = KC + 4 = 68 floats (16B-aligned rows, conflict-free reads)

// Transposed weights: Wt[k][e]  (k-major rows of 64 experts, contiguous)
__device__ float g_Wt[DIM * NEXP];

// ---------- f32x2 helpers (packed fp32 pair ops, sm_103a) ----------
__device__ __forceinline__ unsigned long long pack2(float lo, float hi) {
    unsigned long long r;
    asm("mov.b64 %0, {%1, %2};" : "=l"(r) : "f"(lo), "f"(hi));
    return r;
}
__device__ __forceinline__ void unpack2(unsigned long long v, float& lo, float& hi) {
    asm("mov.b64 {%0, %1}, %2;" : "=f"(lo), "=f"(hi) : "l"(v));
}
__device__ __forceinline__ unsigned long long fma2(unsigned long long a,
                                                   unsigned long long b,
                                                   unsigned long long c) {
    unsigned long long d;
    asm("fma.rn.f32x2 %0, %1, %2, %3;" : "=l"(d) : "l"(a), "l"(b), "l"(c));
    return d;
}

// ---------- kernel 1: transpose W [64][2048] -> Wt [2048][64] ----------
__global__ void transpose_W_kernel(const float* __restrict__ W) {
    int i = blockIdx.x * blockDim.x + threadIdx.x;
    if (i < DIM * NEXP) {
        int e = i / DIM;
        int k = i - e * DIM;
        g_Wt[k * NEXP + e] = W[i];   // coalesced read over k
    }
}

// ---------- kernel 2: fused gate GEMM + top-2 + softmax ----------
__global__ __launch_bounds__(THREADS)
void gate_topk_kernel(const float* __restrict__ inp,
                      const float* __restrict__ bias,
                      float* __restrict__ out,
                      int out_size) {
    __shared__ float Wsm[KC][NEXP];            // 16 KB, rows 256B (16B aligned)
    __shared__ float Xsm[TOK_PER_BLK][KC + XPAD]; // 17.4 KB, rows 272B (16B aligned)

    const int tid  = threadIdx.x;
    const int sub  = tid & 7;        // expert-group lane (0..7)
    const int pair = tid >> 3;       // token-pair (0..31)
    const int e0   = sub * 8;        // first of this thread's 8 experts
    const int tokBase = blockIdx.x * TOK_PER_BLK;
    const int tok0 = tokBase + pair * 2;   // this thread's two tokens: tok0, tok0+1

    // 8 f32x2 accumulators: [token(2)][expert-pair(4)], init with bias
    unsigned long long acc[2][4];
#pragma unroll
    for (int p = 0; p < 4; p++) {
        unsigned long long bv = pack2(bias[e0 + 2 * p], bias[e0 + 2 * p + 1]);
        acc[0][p] = bv;
        acc[1][p] = bv;
    }

    const float* xrow0 = &Xsm[2 * pair][0];
    const float* xrow1 = &Xsm[2 * pair + 1][0];

    for (int k0 = 0; k0 < DIM; k0 += KC) {
        // ---- stage W chunk: KC*NEXP = 4096 floats = 1024 float4 ----
        {
            const float4* src = (const float4*)(g_Wt + (size_t)k0 * NEXP);
            float4* dst = (float4*)(&Wsm[0][0]);
#pragma unroll
            for (int i = 0; i < 4; i++)
                dst[tid + i * THREADS] = src[tid + i * THREADS];
        }
        // ---- stage X chunk: 64 tokens x KC floats; 4 threads per token ----
        {
            int lt = tid >> 2;       // local token 0..63
            int q  = tid & 3;        // quarter of the KC row
            const float4* s = (const float4*)(inp + (size_t)(tokBase + lt) * DIM + k0 + q * 16);
            float4* d = (float4*)&Xsm[lt][q * 16];
#pragma unroll
            for (int i = 0; i < 4; i++) d[i] = s[i];
        }
        __syncthreads();

#pragma unroll 8
        for (int k = 0; k < KC; k++) {
            float x0 = xrow0[k];
            float x1 = xrow1[k];
            unsigned long long X0 = pack2(x0, x0);
            unsigned long long X1 = pack2(x1, x1);
            ulonglong2 WA = *(const ulonglong2*)&Wsm[k][e0];       // experts e0..e0+3
            ulonglong2 WB = *(const ulonglong2*)&Wsm[k][e0 + 4];   // experts e0+4..e0+7
            acc[0][0] = fma2(WA.x, X0, acc[0][0]);
            acc[0][1] = fma2(WA.y, X0, acc[0][1]);
            acc[0][2] = fma2(WB.x, X0, acc[0][2]);
            acc[0][3] = fma2(WB.y, X0, acc[0][3]);
            acc[1][0] = fma2(WA.x, X1, acc[1][0]);
            acc[1][1] = fma2(WA.y, X1, acc[1][1]);
            acc[1][2] = fma2(WB.x, X1, acc[1][2]);
            acc[1][3] = fma2(WB.y, X1, acc[1][3]);
        }
        __syncthreads();
    }

    // ---- top-2 over this thread's 8 experts, per token ----
    const int half = out_size >> 1;   // scores start here (expected 32768)

#pragma unroll
    for (int t = 0; t < 2; t++) {
        float v0 = -3.4e38f, v1 = -3.4e38f;
        int   i0 = -1,       i1 = -1;
#pragma unroll
        for (int p = 0; p < 4; p++) {
            float flo, fhi;
            unpack2(acc[t][p], flo, fhi);
            int elo = e0 + 2 * p, ehi = elo + 1;
            // scan in ascending index order: strict > keeps earliest on ties
            if (flo > v0) { v1 = v0; i1 = i0; v0 = flo; i0 = elo; }
            else if (flo > v1) { v1 = flo; i1 = elo; }
            if (fhi > v0) { v1 = v0; i1 = i0; v0 = fhi; i0 = ehi; }
            else if (fhi > v1) { v1 = fhi; i1 = ehi; }
        }
        // butterfly merge across the 8 lanes sharing this token
#pragma unroll
        for (int ofs = 1; ofs < 8; ofs <<= 1) {
            float u0 = __shfl_xor_sync(0xFFFFFFFFu, v0, ofs);
            float u1 = __shfl_xor_sync(0xFFFFFFFFu, v1, ofs);
            int   j0 = __shfl_xor_sync(0xFFFFFFFFu, i0, ofs);
            int   j1 = __shfl_xor_sync(0xFFFFFFFFu, i1, ofs);
            bool afirst = (v0 > u0) || (v0 == u0 && i0 < j0);
            float nv0, nv1; int ni0, ni1;
            if (afirst) {
                nv0 = v0; ni0 = i0;
                bool s = (u0 > v1) || (u0 == v1 && j0 < i1);
                nv1 = s ? u0 : v1; ni1 = s ? j0 : i1;
            } else {
                nv0 = u0; ni0 = j0;
                bool s = (v0 > u1) || (v0 == u1 && i0 < j1);
                nv1 = s ? v0 : u1; ni1 = s ? i0 : j1;
            }
            v0 = nv0; v1 = nv1; i0 = ni0; i1 = ni1;
        }
        if (sub == 0) {
            int tok = tok0 + t;
            // softmax over (v0 >= v1): s0 = 1/(1+e^(v1-v0))
            float e  = expf(v1 - v0);
            float s0 = 1.0f / (1.0f + e);
            float s1 = e * s0;
            out[tok * 2 + 0] = (float)i0;
            out[tok * 2 + 1] = (float)i1;
            out[half + tok * 2 + 0] = s0;
            out[half + tok * 2 + 1] = s1;
        }
    }
}

extern "C" void kernel_launch(void* const* d_in, const int* in_sizes, int n_in,
                              void* d_out, int out_size) {
    const float* inp  = (const float*)d_in[0];   // [16384, 2048]
    const float* W    = (const float*)d_in[1];   // [64, 2048]
    const float* bias = (const float*)d_in[2];   // [64]
    float* out = (float*)d_out;

    transpose_W_kernel<<<(DIM * NEXP + 255) / 256, 256>>>(W);
    gate_topk_kernel<<<NTOK / TOK_PER_BLK, THREADS>>>(inp, bias, out, out_size);
}

// round 2
// speedup vs baseline: 2.0913x; 2.0913x over previous
#include <cuda_runtime.h>

#define NTOK 16384
#define NEXP 64
#define DIM  2048
#define SPLITS 2
#define KSPLIT (DIM / SPLITS)    // 1024
#define KC 32
#define CHUNKS (KSPLIT / KC)     // 32
#define TOKB 64
#define GTHREADS 128
#define XROW 33                  // KC+1 ull per token row: 264B -> 4-row stride 1056 ≡ 32 (mod 128), bank-clean

typedef unsigned long long ull;

// W pre-permuted: g_Wt2[k][slot] so a warp's 8 concurrent 16B reads are contiguous per 128B line
__device__ float g_Wt2[DIM * NEXP];
// split-K partial logits [split][tok][exp] (8 MB, stays in L2)
__device__ float g_partial[SPLITS * NTOK * NEXP];

// ---------- f32x2 helpers ----------
__device__ __forceinline__ ull pack2(float lo, float hi) {
    ull r;
    asm("mov.b64 %0, {%1, %2};" : "=l"(r) : "f"(lo), "f"(hi));
    return r;
}
__device__ __forceinline__ void unpack2(ull v, float& lo, float& hi) {
    asm("mov.b64 {%0, %1}, %2;" : "=f"(lo), "=f"(hi) : "l"(v));
}
__device__ __forceinline__ ull fma2(ull a, ull b, ull c) {
    ull d;
    asm("fma.rn.f32x2 %0, %1, %2, %3;" : "=l"(d) : "l"(a), "l"(b), "l"(c));
    return d;
}

// ---------- kernel 1: transpose + permute W ----------
// slot order per k-row: even chunks (0,2,..,14) occupy first 128B, odd chunks second 128B.
// Thread with expert-group s reads slot s (experts 8s..8s+3) and slot 8+s (experts 8s+4..8s+7).
__global__ void prep_W(const float* __restrict__ W) {
    int i = blockIdx.x * blockDim.x + threadIdx.x;
    if (i < DIM * NEXP) {
        int e = i >> 11;          // / DIM
        int k = i & (DIM - 1);
        int chunk = e >> 2, w = e & 3;
        int slot = (chunk & 1) ? (8 + (chunk >> 1)) : (chunk >> 1);
        g_Wt2[k * NEXP + slot * 4 + w] = W[i];
    }
}

// ---------- kernel 2: split-K GEMM (no bias, writes partial logits) ----------
__global__ __launch_bounds__(GTHREADS, 4)
void gate_gemm_kernel(const float* __restrict__ inp) {
    __shared__ __align__(128) float Wsm[KC * NEXP];       // 8 KB, single buffer (reg-prefetch)
    __shared__ __align__(128) ull   Xsm[2][TOKB * XROW];  // 33 KB, double buffered, pre-duplicated

    const int tid = threadIdx.x;
    const int sub = tid & 7;        // expert group (8 experts)
    const int q   = tid >> 3;       // token quad 0..15
    const int split   = blockIdx.x & 1;
    const int tokBase = (blockIdx.x >> 1) * TOKB;
    const int kOff    = split * KSPLIT;

    ull acc[4][4];
#pragma unroll
    for (int j = 0; j < 4; j++)
#pragma unroll
        for (int p = 0; p < 4; p++) acc[j][p] = 0ull;

    // ---- initial stage: X chunk 0 + W chunk 0 ----
    {
        const int kb = kOff;
#pragma unroll
        for (int i = 0; i < 4; i++) {
            int f = tid + i * GTHREADS;        // 0..511
            int lt = f >> 3, fq = f & 7;
            float4 v = *(const float4*)(inp + (size_t)(tokBase + lt) * DIM + kb + fq * 4);
            ull* d = &Xsm[0][lt * XROW + fq * 4];
            d[0] = pack2(v.x, v.x); d[1] = pack2(v.y, v.y);
            d[2] = pack2(v.z, v.z); d[3] = pack2(v.w, v.w);
        }
        const float4* ws = (const float4*)(g_Wt2 + (size_t)kOff * NEXP);
        float4* wd = (float4*)Wsm;
#pragma unroll
        for (int i = 0; i < 4; i++) wd[tid + i * GTHREADS] = ws[tid + i * GTHREADS];
    }
    __syncthreads();

    const float* wbase = Wsm + sub * 4;

    for (int c = 0; c < CHUNKS; c++) {
        const int cur = c & 1;
        float4 wreg[4];
        const bool hasNext = (c + 1 < CHUNKS);

        if (hasNext) {
            // prefetch next W chunk into registers (LDG overlaps compute)
            const float4* ws = (const float4*)(g_Wt2 + (size_t)(kOff + (c + 1) * KC) * NEXP);
#pragma unroll
            for (int i = 0; i < 4; i++) wreg[i] = ws[tid + i * GTHREADS];
            // stage next X chunk into alt buffer (LDG+STS overlap compute)
            const int kb = kOff + (c + 1) * KC;
            ull* xb = Xsm[cur ^ 1];
#pragma unroll
            for (int i = 0; i < 4; i++) {
                int f = tid + i * GTHREADS;
                int lt = f >> 3, fq = f & 7;
                float4 v = *(const float4*)(inp + (size_t)(tokBase + lt) * DIM + kb + fq * 4);
                ull* d = &xb[lt * XROW + fq * 4];
                d[0] = pack2(v.x, v.x); d[1] = pack2(v.y, v.y);
                d[2] = pack2(v.z, v.z); d[3] = pack2(v.w, v.w);
            }
        }

        // ---- compute chunk: 4 tokens x 8 experts per thread ----
        {
            const ull* x0 = &Xsm[cur][(4 * q + 0) * XROW];
            const ull* x1 = &Xsm[cur][(4 * q + 1) * XROW];
            const ull* x2 = &Xsm[cur][(4 * q + 2) * XROW];
            const ull* x3 = &Xsm[cur][(4 * q + 3) * XROW];
#pragma unroll 4
            for (int k = 0; k < KC; k++) {
                ulonglong2 WA = *(const ulonglong2*)(wbase + k * NEXP);        // experts 8s..8s+3
                ulonglong2 WB = *(const ulonglong2*)(wbase + k * NEXP + 32);   // experts 8s+4..8s+7
                ull xv0 = x0[k], xv1 = x1[k], xv2 = x2[k], xv3 = x3[k];
                acc[0][0] = fma2(WA.x, xv0, acc[0][0]);
                acc[0][1] = fma2(WA.y, xv0, acc[0][1]);
                acc[0][2] = fma2(WB.x, xv0, acc[0][2]);
                acc[0][3] = fma2(WB.y, xv0, acc[0][3]);
                acc[1][0] = fma2(WA.x, xv1, acc[1][0]);
                acc[1][1] = fma2(WA.y, xv1, acc[1][1]);
                acc[1][2] = fma2(WB.x, xv1, acc[1][2]);
                acc[1][3] = fma2(WB.y, xv1, acc[1][3]);
                acc[2][0] = fma2(WA.x, xv2, acc[2][0]);
                acc[2][1] = fma2(WA.y, xv2, acc[2][1]);
                acc[2][2] = fma2(WB.x, xv2, acc[2][2]);
                acc[2][3] = fma2(WB.y, xv2, acc[2][3]);
                acc[3][0] = fma2(WA.x, xv3, acc[3][0]);
                acc[3][1] = fma2(WA.y, xv3, acc[3][1]);
                acc[3][2] = fma2(WB.x, xv3, acc[3][2]);
                acc[3][3] = fma2(WB.y, xv3, acc[3][3]);
            }
        }
        __syncthreads();              // compute(c) done + X(c+1) stored
        if (hasNext) {
            float4* wd = (float4*)Wsm;
#pragma unroll
            for (int i = 0; i < 4; i++) wd[tid + i * GTHREADS] = wreg[i];
        }
        __syncthreads();              // Wsm ready for chunk c+1
    }

    // ---- write partial logits: experts 8*sub..8*sub+7 for 4 tokens ----
#pragma unroll
    for (int j = 0; j < 4; j++) {
        int tok = tokBase + 4 * q + j;
        float* dst = g_partial + ((size_t)split * NTOK + tok) * NEXP + sub * 8;
        ulonglong2 s0; s0.x = acc[j][0]; s0.y = acc[j][1];
        ulonglong2 s1; s1.x = acc[j][2]; s1.y = acc[j][3];
        *(ulonglong2*)(dst)     = s0;
        *(ulonglong2*)(dst + 4) = s1;
    }
}

// ---------- kernel 3: reduce splits + bias + top-2 + softmax ----------
__global__ __launch_bounds__(256)
void reduce_topk(const float* __restrict__ bias, float* __restrict__ out, int out_size) {
    const int tid = threadIdx.x;
    const int sub = tid & 7;
    const int lt  = tid >> 3;                 // 0..31
    const int tok = blockIdx.x * 32 + lt;
    const int e0  = sub * 8;
    const int half = out_size >> 1;

    const float4* p0 = (const float4*)(g_partial + (size_t)tok * NEXP + e0);
    const float4* p1 = (const float4*)(g_partial + ((size_t)NTOK + tok) * NEXP + e0);
    float4 a0 = p0[0], a1 = p0[1];
    float4 b0 = p1[0], b1 = p1[1];
    float4 c0 = *(const float4*)(bias + e0);
    float4 c1 = *(const float4*)(bias + e0 + 4);

    float v[8] = { a0.x + b0.x + c0.x, a0.y + b0.y + c0.y,
                   a0.z + b0.z + c0.z, a0.w + b0.w + c0.w,
                   a1.x + b1.x + c1.x, a1.y + b1.y + c1.y,
                   a1.z + b1.z + c1.z, a1.w + b1.w + c1.w };

    // local top-2 (ascending index scan; strict > keeps lowest index on ties)
    float v0 = -3.4e38f, v1 = -3.4e38f;
    int   i0 = -1,       i1 = -1;
#pragma unroll
    for (int j = 0; j < 8; j++) {
        float f = v[j]; int e = e0 + j;
        if (f > v0)      { v1 = v0; i1 = i0; v0 = f; i0 = e; }
        else if (f > v1) { v1 = f;  i1 = e; }
    }
    // butterfly merge across the 8 lanes of this token
#pragma unroll
    for (int ofs = 1; ofs < 8; ofs <<= 1) {
        float u0 = __shfl_xor_sync(0xFFFFFFFFu, v0, ofs);
        float u1 = __shfl_xor_sync(0xFFFFFFFFu, v1, ofs);
        int   j0 = __shfl_xor_sync(0xFFFFFFFFu, i0, ofs);
        int   j1 = __shfl_xor_sync(0xFFFFFFFFu, i1, ofs);
        bool afirst = (v0 > u0) || (v0 == u0 && i0 < j0);
        float nv0, nv1; int ni0, ni1;
        if (afirst) {
            nv0 = v0; ni0 = i0;
            bool s = (u0 > v1) || (u0 == v1 && j0 < i1);
            nv1 = s ? u0 : v1; ni1 = s ? j0 : i1;
        } else {
            nv0 = u0; ni0 = j0;
            bool s = (v0 > u1) || (v0 == u1 && i0 < j1);
            nv1 = s ? v0 : u1; ni1 = s ? i0 : j1;
        }
        v0 = nv0; v1 = nv1; i0 = ni0; i1 = ni1;
    }
    if (sub == 0) {
        float e  = expf(v1 - v0);
        float s0 = 1.0f / (1.0f + e);
        float s1 = e * s0;
        out[tok * 2 + 0] = (float)i0;
        out[tok * 2 + 1] = (float)i1;
        out[half + tok * 2 + 0] = s0;
        out[half + tok * 2 + 1] = s1;
    }
}

extern "C" void kernel_launch(void* const* d_in, const int* in_sizes, int n_in,
                              void* d_out, int out_size) {
    const float* inp  = (const float*)d_in[0];   // [16384, 2048]
    const float* W    = (const float*)d_in[1];   // [64, 2048]
    const float* bias = (const float*)d_in[2];   // [64]
    float* out = (float*)d_out;

    prep_W<<<(DIM * NEXP + 255) / 256, 256>>>(W);
    gate_gemm_kernel<<<SPLITS * (NTOK / TOKB), GTHREADS>>>(inp);
    reduce_topk<<<NTOK / 32, 256>>>(bias, out, out_size);
}